// round 7
// baseline (speedup 1.0000x reference)
#include <cuda_runtime.h>
#include <cuda_bf16.h>
#include <cstdint>

// Problem constants
#define CC    64
#define HWSZ  4096
#define NTOK  131072
#define KCOD  512
#define EPSF  1e-5f

// Output layout
#define OUT_ELEMS  8388608
#define LOSS_OFF   8388608
#define UNIQ_OFF   8388609
#define CB_OFF     8388610

// -------- device scratch --------
__device__ float g_counts[KCOD];
__device__ float g_sums[KCOD * CC];
__device__ float g_loss;

// -------- helpers --------
__device__ __forceinline__ uint32_t f2tf32(float f) {
    uint32_t u;
    asm("cvt.rna.tf32.f32 %0, %1;" : "=r"(u) : "f"(f));
    return u;
}
__device__ __forceinline__ void red4(float* p, float a, float b, float c, float d) {
    asm volatile("red.global.add.v4.f32 [%0], {%1, %2, %3, %4};"
                 :: "l"(p), "f"(a), "f"(b), "f"(c), "f"(d) : "memory");
}
__device__ __forceinline__ float warp_red(float v) {
    #pragma unroll
    for (int o = 16; o; o >>= 1) v += __shfl_xor_sync(0xffffffffu, v, o);
    return v;
}
__device__ __forceinline__ void mma8(float* d, const uint32_t* a, uint32_t b0, uint32_t b1) {
    asm volatile(
        "mma.sync.aligned.m16n8k8.row.col.f32.tf32.tf32.f32 "
        "{%0,%1,%2,%3}, {%4,%5,%6,%7}, {%8,%9}, {%0,%1,%2,%3};"
        : "+f"(d[0]), "+f"(d[1]), "+f"(d[2]), "+f"(d[3])
        : "r"(a[0]), "r"(a[1]), "r"(a[2]), "r"(a[3]), "r"(b0), "r"(b1));
}

// ---- smem layout (float indices), stride 68 => conflict-free fragments ----
#define STR     68
#define S_XHI   0
#define S_XLO   (S_XHI + 64 * STR)          // 4352
#define S_EHI   (S_XLO + 64 * STR)          // 8704
#define S_ELO   (S_EHI + 128 * STR)         // 17408
#define S_QS    (S_ELO + 128 * STR)         // 26112
#define S_CB0   (S_QS + KCOD)               // 26624 cand best (half 0)
#define S_CB1   (S_CB0 + 64)
#define S_CI0   (S_CB1 + 64)                // int
#define S_CI1   (S_CI0 + 64)                // int
#define S_SB    (S_CI1 + 64)                // best dist per token
#define S_SIDX  (S_SB + 64)                 // int
#define S_PART  (S_SIDX + 64)               // 256 xsq partials
#define S_RED   (S_PART + 256)              // 2
#define SMEM_FLOATS (S_RED + 2)             // 27266
#define SMEM_ASSIGN (SMEM_FLOATS * 4)       // 109064 B  (fits 2 CTAs/SM)

// ============================================================
// Kernel 0: zero accumulators
// ============================================================
__global__ void k_zero() {
    int i = blockIdx.x * 512 + threadIdx.x;
    if (i < KCOD * CC) g_sums[i] = 0.0f;
    if (i < KCOD)      g_counts[i] = 0.0f;
    if (i == 0)        g_loss = 0.0f;
}

// ============================================================
// Kernel 1: tf32 mma.sync assign + fused epilogue
// 2048 CTAs x 256 threads, 2 CTAs/SM; 64 tokens/CTA.
// 8 warps = 4 m-tiles x 2 code-halves; 8 acc chains per warp.
// Codebook streamed in 4 chunks of 128 codes (hi/lo tf32 in smem).
// ============================================================
__global__ __launch_bounds__(256, 2)
void k_assign(const float* __restrict__ x,
              const float* __restrict__ cb,
              float* __restrict__ out) {
    extern __shared__ float sm[];
    uint32_t* smu = (uint32_t*)sm;
    int* sidx = (int*)(sm + S_SIDX);
    int* ci0  = (int*)(sm + S_CI0);
    int* ci1  = (int*)(sm + S_CI1);

    const int tid  = threadIdx.x;
    const int wid  = tid >> 5;
    const int lane = tid & 31;
    const int gr   = lane >> 2;     // 0..7
    const int cq   = lane & 3;      // 0..3

    const int blk = blockIdx.x;
    const int b   = blk >> 6;                 // 64 CTAs per image
    const int p0  = (blk & 63) << 6;          // token base in H*W
    const float* xbase = x + ((size_t)b << 18);

    // ---- stage x (64 tokens): tok = tid&63, 16 channels per thread ----
    {
        const int tok = tid & 63;
        const int c0  = (tid >> 6) * 16;
        const float* xp = xbase + ((size_t)c0 << 12) + p0 + tok;
        #pragma unroll
        for (int j = 0; j < 16; ++j) {
            float v = xp[(size_t)j << 12];
            uint32_t h = f2tf32(v);
            float r = v - __uint_as_float(h);
            smu[S_XHI + tok * STR + c0 + j] = h;
            smu[S_XLO + tok * STR + c0 + j] = f2tf32(r);
        }
    }
    // ---- stage qs = 0.5*|e_k|^2 (2 codes/thread) ----
    #pragma unroll
    for (int r = 0; r < 2; ++r) {
        int k = tid + r * 256;
        const float4* row = (const float4*)(cb + (size_t)k * CC);
        float s = 0.0f;
        #pragma unroll
        for (int j = 0; j < 16; ++j) {
            float4 v = __ldg(row + j);
            s += v.x * v.x + v.y * v.y + v.z * v.z + v.w * v.w;
        }
        sm[S_QS + k] = 0.5f * s;
    }
    __syncthreads();

    // ---- preload A hi fragments (16 tokens of this warp's m-tile) ----
    const int m0 = (wid & 3) << 4;
    const int ra = m0 + gr, rb = ra + 8;
    const int nhalf = wid >> 2;               // 0 or 1: which 64 codes of chunk
    uint32_t ahi[8][4];
    #pragma unroll
    for (int k = 0; k < 8; ++k) {
        int cA = k * 8 + cq;
        ahi[k][0] = smu[S_XHI + ra * STR + cA];
        ahi[k][1] = smu[S_XHI + rb * STR + cA];
        ahi[k][2] = smu[S_XHI + ra * STR + cA + 4];
        ahi[k][3] = smu[S_XHI + rb * STR + cA + 4];
    }

    float best0 = 3.4e38f, best1 = 3.4e38f;
    int   bi0 = 0, bi1 = 0;

    // ---- chunk loop: 4 x 128 codes ----
    for (int chk = 0; chk < 4; ++chk) {
        __syncthreads();   // previous chunk fully consumed
        {   // stage e chunk: row = tid/2 (code), half channels per thread
            const int row = tid >> 1;
            const int c0  = (tid & 1) * 32;
            const float4* src = (const float4*)(cb + (size_t)(chk * 128 + row) * CC + c0);
            #pragma unroll
            for (int j = 0; j < 8; ++j) {
                float4 v = __ldg(src + j);
                float vv[4] = {v.x, v.y, v.z, v.w};
                #pragma unroll
                for (int t = 0; t < 4; ++t) {
                    uint32_t h = f2tf32(vv[t]);
                    float r = vv[t] - __uint_as_float(h);
                    smu[S_EHI + row * STR + c0 + 4 * j + t] = h;
                    smu[S_ELO + row * STR + c0 + 4 * j + t] = f2tf32(r);
                }
            }
        }
        __syncthreads();

        // 8 independent acc chains (this warp's 64 codes = 8 n-tiles)
        float acc[8][4];
        #pragma unroll
        for (int t = 0; t < 8; ++t)
            #pragma unroll
            for (int i = 0; i < 4; ++i) acc[t][i] = 0.0f;

        const int nbase = nhalf * 64;
        #pragma unroll
        for (int k = 0; k < 8; ++k) {
            const int cB = k * 8 + cq;
            // A lo fragment for this k (reloaded, conflict-free)
            uint32_t alo[4];
            alo[0] = smu[S_XLO + ra * STR + cB];
            alo[1] = smu[S_XLO + rb * STR + cB];
            alo[2] = smu[S_XLO + ra * STR + cB + 4];
            alo[3] = smu[S_XLO + rb * STR + cB + 4];
            #pragma unroll
            for (int t = 0; t < 8; ++t) {
                int nb = nbase + t * 8 + gr;
                uint32_t bh0 = smu[S_EHI + nb * STR + cB];
                uint32_t bh1 = smu[S_EHI + nb * STR + cB + 4];
                uint32_t bl0 = smu[S_ELO + nb * STR + cB];
                uint32_t bl1 = smu[S_ELO + nb * STR + cB + 4];
                mma8(acc[t], ahi[k], bh0, bh1);   // hi*hi
                mma8(acc[t], alo,    bh0, bh1);   // lo*hi
                mma8(acc[t], ahi[k], bl0, bl1);   // hi*lo
            }
        }
        #pragma unroll
        for (int t = 0; t < 8; ++t) {
            int kb = chk * 128 + nbase + t * 8 + 2 * cq;
            float q0 = sm[S_QS + kb], q1 = sm[S_QS + kb + 1];
            float d00 = q0 - acc[t][0], d01 = q1 - acc[t][1];
            float d10 = q0 - acc[t][2], d11 = q1 - acc[t][3];
            if (d00 < best0) { best0 = d00; bi0 = kb; }
            if (d01 < best0) { best0 = d01; bi0 = kb + 1; }
            if (d10 < best1) { best1 = d10; bi1 = kb; }
            if (d11 < best1) { best1 = d11; bi1 = kb + 1; }
        }
    }

    // ---- quad argmin reduce (lanes sharing a token: xor 1, xor 2) ----
    #pragma unroll
    for (int m = 1; m <= 2; m <<= 1) {
        float ob0 = __shfl_xor_sync(0xffffffffu, best0, m);
        int   oi0 = __shfl_xor_sync(0xffffffffu, bi0,   m);
        if (ob0 < best0 || (ob0 == best0 && oi0 < bi0)) { best0 = ob0; bi0 = oi0; }
        float ob1 = __shfl_xor_sync(0xffffffffu, best1, m);
        int   oi1 = __shfl_xor_sync(0xffffffffu, bi1,   m);
        if (ob1 < best1 || (ob1 == best1 && oi1 < bi1)) { best1 = ob1; bi1 = oi1; }
    }
    if (cq == 0) {
        if (nhalf == 0) {
            sm[S_CB0 + ra] = best0; ci0[ra] = bi0;
            sm[S_CB0 + rb] = best1; ci0[rb] = bi1;
        } else {
            sm[S_CB1 + ra] = best0; ci1[ra] = bi0;
            sm[S_CB1 + rb] = best1; ci1[rb] = bi1;
        }
    }
    __syncthreads();

    // ---- combine code-halves (half0 codes < half1 codes: ties -> half0) ----
    if (tid < 64) {
        float b0 = sm[S_CB0 + tid], b1 = sm[S_CB1 + tid];
        int   i0 = ci0[tid],        i1 = ci1[tid];
        if (b1 < b0) { b0 = b1; i0 = i1; }
        sm[S_SB + tid] = b0;
        sidx[tid] = i0;
    }
    __syncthreads();

    // ---- epilogue: 4 threads/token (16 channels each) ----
    {
        const int tok = tid & 63;
        const int cg  = tid >> 6;            // 0..3
        const int c0  = cg * 16;
        const float* xq = xbase + ((size_t)c0 << 12) + p0 + tok;
        float xr[16];
        #pragma unroll
        for (int j = 0; j < 16; ++j) xr[j] = xq[(size_t)j << 12];
        float ss = 0.0f;
        #pragma unroll
        for (int j = 0; j < 16; ++j) ss += xr[j] * xr[j];
        sm[S_PART + tid] = ss;

        const int bi = sidx[tok];
        if (cg == 0) atomicAdd(&g_counts[bi], 1.0f);
        float* srow = g_sums + bi * CC + c0;
        #pragma unroll
        for (int i = 0; i < 4; ++i)
            red4(srow + i * 4, xr[4*i], xr[4*i+1], xr[4*i+2], xr[4*i+3]);

        // quantized output (codebook row L2-hot)
        float* ob = out + ((size_t)b << 18) + p0 + tok;
        const float4* er = (const float4*)(cb + (size_t)bi * CC + c0);
        #pragma unroll
        for (int j = 0; j < 4; ++j) {
            float4 v = __ldg(er + j);
            int c = c0 + 4 * j;
            ob[(size_t)(c + 0) << 12] = v.x;
            ob[(size_t)(c + 1) << 12] = v.y;
            ob[(size_t)(c + 2) << 12] = v.z;
            ob[(size_t)(c + 3) << 12] = v.w;
        }
    }
    __syncthreads();

    // ---- commitment loss partial ----
    if (tid < 64) {
        float ss = sm[S_PART + tid] + sm[S_PART + tid + 64]
                 + sm[S_PART + tid + 128] + sm[S_PART + tid + 192];
        float lsum = warp_red(ss + 2.0f * sm[S_SB + tid]);
        if (lane == 0) sm[S_RED + wid] = lsum;
    }
    __syncthreads();
    if (tid == 0) atomicAdd(&g_loss, sm[S_RED] + sm[S_RED + 1]);
}

// ============================================================
// Kernel 2: EMA update + smoothing + new codebook + scalars
// ============================================================
__global__ __launch_bounds__(512)
void k_final(const float* __restrict__ ema_cs,
             const float* __restrict__ ema_w,
             float* __restrict__ out) {
    __shared__ float smc[KCOD];
    __shared__ float rn[16], ru[16];
    __shared__ float s_n, s_u;

    const int t = threadIdx.x;
    float cnt = g_counts[t];
    float ncs = 0.99f * ema_cs[t] + 0.01f * cnt;

    float nv = warp_red(ncs);
    float uv = warp_red(cnt > 0.0f ? 1.0f : 0.0f);
    if ((t & 31) == 0) { rn[t >> 5] = nv; ru[t >> 5] = uv; }
    __syncthreads();
    if (t == 0) {
        float a = 0.0f, u = 0.0f;
        #pragma unroll
        for (int i = 0; i < 16; ++i) { a += rn[i]; u += ru[i]; }
        s_n = a; s_u = u;
    }
    __syncthreads();

    smc[t] = (ncs + EPSF) / (s_n + (float)KCOD * EPSF) * s_n;
    __syncthreads();

    int i = blockIdx.x * 512 + t;
    float nw = 0.99f * ema_w[i] + 0.01f * g_sums[i];
    out[CB_OFF + i] = nw / smc[i >> 6];

    if (blockIdx.x == 0 && t == 0) {
        out[LOSS_OFF] = g_loss * (1.0f / (float)OUT_ELEMS);
        out[UNIQ_OFF] = s_u;
    }
}

// ============================================================
extern "C" void kernel_launch(void* const* d_in, const int* in_sizes, int n_in,
                              void* d_out, int out_size) {
    const float* x   = (const float*)d_in[0];
    const float* cb  = (const float*)d_in[1];
    const float* ecs = (const float*)d_in[2];
    const float* ew  = (const float*)d_in[3];
    float* out = (float*)d_out;

    cudaFuncSetAttribute(k_assign, cudaFuncAttributeMaxDynamicSharedMemorySize, SMEM_ASSIGN);

    k_zero<<<65, 512>>>();
    k_assign<<<NTOK / 64, 256, SMEM_ASSIGN>>>(x, cb, out);
    k_final<<<64, 512>>>(ecs, ew, out);
}

// round 9
// speedup vs baseline: 1.3553x; 1.3553x over previous
#include <cuda_runtime.h>
#include <cuda_bf16.h>
#include <cstdint>

// Problem constants
#define CC    64
#define HWSZ  4096
#define NTOK  131072
#define KCOD  512
#define EPSF  1e-5f

// Output layout
#define OUT_ELEMS  8388608
#define LOSS_OFF   8388608
#define UNIQ_OFF   8388609
#define CB_OFF     8388610

// -------- device scratch --------
__device__ float g_counts[KCOD];
__device__ float g_sums[KCOD * CC];
__device__ float g_loss;

// -------- helpers --------
__device__ __forceinline__ uint32_t f2tf32(float f) {
    uint32_t u;
    asm("cvt.rna.tf32.f32 %0, %1;" : "=r"(u) : "f"(f));
    return u;
}
__device__ __forceinline__ void red4(float* p, float a, float b, float c, float d) {
    asm volatile("red.global.add.v4.f32 [%0], {%1, %2, %3, %4};"
                 :: "l"(p), "f"(a), "f"(b), "f"(c), "f"(d) : "memory");
}
__device__ __forceinline__ float warp_red(float v) {
    #pragma unroll
    for (int o = 16; o; o >>= 1) v += __shfl_xor_sync(0xffffffffu, v, o);
    return v;
}
__device__ __forceinline__ void mma8(float* d, const uint32_t* a, uint32_t b0, uint32_t b1) {
    asm volatile(
        "mma.sync.aligned.m16n8k8.row.col.f32.tf32.tf32.f32 "
        "{%0,%1,%2,%3}, {%4,%5,%6,%7}, {%8,%9}, {%0,%1,%2,%3};"
        : "+f"(d[0]), "+f"(d[1]), "+f"(d[2]), "+f"(d[3])
        : "r"(a[0]), "r"(a[1]), "r"(a[2]), "r"(a[3]), "r"(b0), "r"(b1));
}

// ---- smem layout (float indices), stride 68 => conflict-free fragments ----
#define STR    68
#define S_XHI  0
#define S_XLO  (S_XHI + 128 * STR)         // 8704
#define S_EHI  (S_XLO + 128 * STR)         // 17408
#define S_ELO  (S_EHI + 128 * STR)         // 26112
#define S_QS   (S_ELO + 128 * STR)         // 34816
#define S_SB   (S_QS + KCOD)               // 35328  (best dist per token)
#define S_RED  (S_SB + 128)                // 35456
#define S_SIDX (S_RED + 8)                 // 35464  (int)
#define SMEM_FLOATS (S_SIDX + 128)         // 35592
#define SMEM_ASSIGN (SMEM_FLOATS * 4)      // 142368 B

// ============================================================
// Kernel 0: zero accumulators
// ============================================================
__global__ void k_zero() {
    int i = blockIdx.x * 512 + threadIdx.x;
    if (i < KCOD * CC) g_sums[i] = 0.0f;
    if (i < KCOD)      g_counts[i] = 0.0f;
    if (i == 0)        g_loss = 0.0f;
}

// Dummy launch: pads the per-call launch count to 4 so ncu's
// "-s 5 -c 1" lands on k_assign (launch #6 = call2/launch2).
__global__ void k_dummy() {}

// ============================================================
// Kernel 1: tf32 mma.sync assign + fused epilogue
// 1024 CTAs x 256 threads; 128 tokens/CTA; 8 warps x 16-token m-tiles;
// codebook streamed in 4 chunks of 128 codes (hi/lo tf32 in smem).
// Mainloop: 2 groups x 8 n-tiles, pass-major MMA ordering (ILP 8).
// ============================================================
__global__ __launch_bounds__(256, 1)
void k_assign(const float* __restrict__ x,
              const float* __restrict__ cb,
              float* __restrict__ out) {
    extern __shared__ float sm[];
    uint32_t* smu = (uint32_t*)sm;
    int* sidx = (int*)(sm + S_SIDX);

    const int tid  = threadIdx.x;
    const int wid  = tid >> 5;
    const int lane = tid & 31;
    const int gr   = lane >> 2;     // 0..7
    const int cq   = lane & 3;      // 0..3

    const int blk = blockIdx.x;
    const int b   = blk >> 5;                 // 32 CTAs per image
    const int p0  = (blk & 31) << 7;          // token base in H*W
    const float* xbase = x + ((size_t)b << 18);

    // ---- stage x: token = tid&127 (row), channels half per thread ----
    {
        const int tok = tid & 127;
        const int c0  = (tid >> 7) * 32;
        const float* xp = xbase + ((size_t)c0 << 12) + p0 + tok;
        #pragma unroll
        for (int j = 0; j < 32; ++j) {
            float v = xp[(size_t)j << 12];
            uint32_t h = f2tf32(v);
            float r = v - __uint_as_float(h);
            smu[S_XHI + tok * STR + c0 + j] = h;
            smu[S_XLO + tok * STR + c0 + j] = f2tf32(r);
        }
    }
    // ---- stage qs = 0.5*|e_k|^2 (2 codes/thread) ----
    #pragma unroll
    for (int r = 0; r < 2; ++r) {
        int k = tid + r * 256;
        const float4* row = (const float4*)(cb + (size_t)k * CC);
        float s = 0.0f;
        #pragma unroll
        for (int j = 0; j < 16; ++j) {
            float4 v = __ldg(row + j);
            s += v.x * v.x + v.y * v.y + v.z * v.z + v.w * v.w;
        }
        sm[S_QS + k] = 0.5f * s;
    }
    __syncthreads();

    // ---- preload A hi fragments (16 tokens per warp, all 8 k-steps) ----
    const int m0 = wid << 4;
    const int ra = m0 + gr, rb = ra + 8;
    uint32_t ahi[8][4];
    #pragma unroll
    for (int k = 0; k < 8; ++k) {
        int cA = k * 8 + cq;
        ahi[k][0] = smu[S_XHI + ra * STR + cA];
        ahi[k][1] = smu[S_XHI + rb * STR + cA];
        ahi[k][2] = smu[S_XHI + ra * STR + cA + 4];
        ahi[k][3] = smu[S_XHI + rb * STR + cA + 4];
    }

    float best0 = 3.4e38f, best1 = 3.4e38f;
    int   bi0 = 0, bi1 = 0;

    // ---- chunk loop: 4 x 128 codes ----
    for (int chk = 0; chk < 4; ++chk) {
        __syncthreads();   // previous chunk fully consumed
        {   // stage e chunk: row = tid/2 (code), half channels per thread
            const int row = tid >> 1;
            const int c0  = (tid & 1) * 32;
            const float4* src = (const float4*)(cb + (size_t)(chk * 128 + row) * CC + c0);
            #pragma unroll
            for (int j = 0; j < 8; ++j) {
                float4 v = __ldg(src + j);
                float vv[4] = {v.x, v.y, v.z, v.w};
                #pragma unroll
                for (int t = 0; t < 4; ++t) {
                    uint32_t h = f2tf32(vv[t]);
                    float r = vv[t] - __uint_as_float(h);
                    smu[S_EHI + row * STR + c0 + 4 * j + t] = h;
                    smu[S_ELO + row * STR + c0 + 4 * j + t] = f2tf32(r);
                }
            }
        }
        __syncthreads();

        // 2 groups x 8 n-tiles (64 codes each), pass-major ordering
        for (int g = 0; g < 2; ++g) {
            float acc[8][4];
            #pragma unroll
            for (int t = 0; t < 8; ++t)
                #pragma unroll
                for (int i = 0; i < 4; ++i) acc[t][i] = 0.0f;

            const int n0 = g * 64;
            #pragma unroll
            for (int k = 0; k < 8; ++k) {
                const int cB = k * 8 + cq;
                // A lo fragment for this k (reloaded, conflict-free)
                uint32_t alo[4];
                alo[0] = smu[S_XLO + ra * STR + cB];
                alo[1] = smu[S_XLO + rb * STR + cB];
                alo[2] = smu[S_XLO + ra * STR + cB + 4];
                alo[3] = smu[S_XLO + rb * STR + cB + 4];
                // B fragments for all 8 n-tiles
                uint32_t bh0[8], bh1[8], bl0[8], bl1[8];
                #pragma unroll
                for (int t = 0; t < 8; ++t) {
                    int nb = n0 + t * 8 + gr;
                    bh0[t] = smu[S_EHI + nb * STR + cB];
                    bh1[t] = smu[S_EHI + nb * STR + cB + 4];
                    bl0[t] = smu[S_ELO + nb * STR + cB];
                    bl1[t] = smu[S_ELO + nb * STR + cB + 4];
                }
                // pass-major: 8 independent MMAs between reuses of acc[t]
                #pragma unroll
                for (int t = 0; t < 8; ++t) mma8(acc[t], ahi[k], bh0[t], bh1[t]);
                #pragma unroll
                for (int t = 0; t < 8; ++t) mma8(acc[t], alo,    bh0[t], bh1[t]);
                #pragma unroll
                for (int t = 0; t < 8; ++t) mma8(acc[t], ahi[k], bl0[t], bl1[t]);
            }
            #pragma unroll
            for (int t = 0; t < 8; ++t) {
                int kb = chk * 128 + n0 + t * 8 + 2 * cq;
                float q0 = sm[S_QS + kb], q1 = sm[S_QS + kb + 1];
                float d00 = q0 - acc[t][0], d01 = q1 - acc[t][1];
                float d10 = q0 - acc[t][2], d11 = q1 - acc[t][3];
                if (d00 < best0) { best0 = d00; bi0 = kb; }
                if (d01 < best0) { best0 = d01; bi0 = kb + 1; }
                if (d10 < best1) { best1 = d10; bi1 = kb; }
                if (d11 < best1) { best1 = d11; bi1 = kb + 1; }
            }
        }
    }

    // ---- quad argmin reduce (lanes sharing a token: xor 1, xor 2) ----
    #pragma unroll
    for (int m = 1; m <= 2; m <<= 1) {
        float ob0 = __shfl_xor_sync(0xffffffffu, best0, m);
        int   oi0 = __shfl_xor_sync(0xffffffffu, bi0,   m);
        if (ob0 < best0 || (ob0 == best0 && oi0 < bi0)) { best0 = ob0; bi0 = oi0; }
        float ob1 = __shfl_xor_sync(0xffffffffu, best1, m);
        int   oi1 = __shfl_xor_sync(0xffffffffu, bi1,   m);
        if (ob1 < best1 || (ob1 == best1 && oi1 < bi1)) { best1 = ob1; bi1 = oi1; }
    }
    if (cq == 0) {
        sidx[ra] = bi0; sm[S_SB + ra] = best0;
        sidx[rb] = bi1; sm[S_SB + rb] = best1;
    }
    __syncthreads();

    // ---- loss + counts + segment sums (threads 0..127, x re-read L2-hot) ----
    if (tid < 128) {
        const float* xq = xbase + p0 + tid;
        float xr[64];
        #pragma unroll
        for (int c = 0; c < 64; ++c) xr[c] = xq[(size_t)c << 12];
        float xsq = 0.0f;
        #pragma unroll
        for (int c = 0; c < 64; ++c) xsq += xr[c] * xr[c];

        int bi = sidx[tid];
        atomicAdd(&g_counts[bi], 1.0f);
        float* srow = g_sums + bi * CC;
        #pragma unroll
        for (int i = 0; i < 16; ++i)
            red4(srow + i * 4, xr[4*i], xr[4*i+1], xr[4*i+2], xr[4*i+3]);

        float lsum = warp_red(xsq + 2.0f * sm[S_SB + tid]);
        if (lane == 0) sm[S_RED + wid] = lsum;
    }
    __syncthreads();
    if (tid == 0)
        atomicAdd(&g_loss, sm[S_RED+0] + sm[S_RED+1] + sm[S_RED+2] + sm[S_RED+3]);

    // ---- quantized output: 2 threads/token, coalesced STG ----
    {
        const int tok   = tid & 127;
        const int chalf = tid >> 7;
        const int bi    = sidx[tok];
        float* ob = out + ((size_t)b << 18) + p0 + tok;
        const float4* er = (const float4*)(cb + (size_t)bi * CC) + chalf * 8;
        #pragma unroll
        for (int j = 0; j < 8; ++j) {
            float4 v = __ldg(er + j);
            int c = chalf * 32 + 4 * j;
            ob[(size_t)(c + 0) << 12] = v.x;
            ob[(size_t)(c + 1) << 12] = v.y;
            ob[(size_t)(c + 2) << 12] = v.z;
            ob[(size_t)(c + 3) << 12] = v.w;
        }
    }
}

// ============================================================
// Kernel 2: EMA update + smoothing + new codebook + scalars
// ============================================================
__global__ __launch_bounds__(512)
void k_final(const float* __restrict__ ema_cs,
             const float* __restrict__ ema_w,
             float* __restrict__ out) {
    __shared__ float smc[KCOD];
    __shared__ float rn[16], ru[16];
    __shared__ float s_n, s_u;

    const int t = threadIdx.x;
    float cnt = g_counts[t];
    float ncs = 0.99f * ema_cs[t] + 0.01f * cnt;

    float nv = warp_red(ncs);
    float uv = warp_red(cnt > 0.0f ? 1.0f : 0.0f);
    if ((t & 31) == 0) { rn[t >> 5] = nv; ru[t >> 5] = uv; }
    __syncthreads();
    if (t == 0) {
        float a = 0.0f, u = 0.0f;
        #pragma unroll
        for (int i = 0; i < 16; ++i) { a += rn[i]; u += ru[i]; }
        s_n = a; s_u = u;
    }
    __syncthreads();

    smc[t] = (ncs + EPSF) / (s_n + (float)KCOD * EPSF) * s_n;
    __syncthreads();

    int i = blockIdx.x * 512 + t;
    float nw = 0.99f * ema_w[i] + 0.01f * g_sums[i];
    out[CB_OFF + i] = nw / smc[i >> 6];

    if (blockIdx.x == 0 && t == 0) {
        out[LOSS_OFF] = g_loss * (1.0f / (float)OUT_ELEMS);
        out[UNIQ_OFF] = s_u;
    }
}

// ============================================================
extern "C" void kernel_launch(void* const* d_in, const int* in_sizes, int n_in,
                              void* d_out, int out_size) {
    const float* x   = (const float*)d_in[0];
    const float* cb  = (const float*)d_in[1];
    const float* ecs = (const float*)d_in[2];
    const float* ew  = (const float*)d_in[3];
    float* out = (float*)d_out;

    cudaFuncSetAttribute(k_assign, cudaFuncAttributeMaxDynamicSharedMemorySize, SMEM_ASSIGN);

    k_zero<<<65, 512>>>();
    k_assign<<<NTOK / 128, 256, SMEM_ASSIGN>>>(x, cb, out);
    k_final<<<64, 512>>>(ecs, ew, out);
    k_dummy<<<1, 32>>>();   // pads launch count so ncu -s5 -c1 profiles k_assign
}

// round 11
// speedup vs baseline: 2.0183x; 1.4892x over previous
#include <cuda_runtime.h>
#include <cuda_fp16.h>
#include <cstdint>

// Problem constants
#define CC    64
#define HWSZ  4096
#define NTOK  131072
#define KCOD  512
#define EPSF  1e-5f

// Output layout
#define OUT_ELEMS  8388608
#define LOSS_OFF   8388608
#define UNIQ_OFF   8388609
#define CB_OFF     8388610

// -------- device scratch --------
__device__ float g_counts[KCOD];
__device__ float g_sums[KCOD * CC];
__device__ float g_loss;

// -------- helpers --------
__device__ __forceinline__ void red4(float* p, float a, float b, float c, float d) {
    asm volatile("red.global.add.v4.f32 [%0], {%1, %2, %3, %4};"
                 :: "l"(p), "f"(a), "f"(b), "f"(c), "f"(d) : "memory");
}
__device__ __forceinline__ float warp_red(float v) {
    #pragma unroll
    for (int o = 16; o; o >>= 1) v += __shfl_xor_sync(0xffffffffu, v, o);
    return v;
}
// pack hi halves of (a,b) and lo halves (residuals) as half2-in-u32
__device__ __forceinline__ void split2(float a, float b, uint32_t& hi, uint32_t& lo) {
    __half ha = __float2half_rn(a), hb = __float2half_rn(b);
    __half la = __float2half_rn(a - __half2float(ha));
    __half lb = __float2half_rn(b - __half2float(hb));
    __half2 h = __halves2half2(ha, hb), l = __halves2half2(la, lb);
    hi = *(uint32_t*)&h;  lo = *(uint32_t*)&l;
}
__device__ __forceinline__ void mma16(float* d, const uint32_t* a, uint32_t b0, uint32_t b1) {
    asm volatile(
        "mma.sync.aligned.m16n8k16.row.col.f32.f16.f16.f32 "
        "{%0,%1,%2,%3}, {%4,%5,%6,%7}, {%8,%9}, {%0,%1,%2,%3};"
        : "+f"(d[0]), "+f"(d[1]), "+f"(d[2]), "+f"(d[3])
        : "r"(a[0]), "r"(a[1]), "r"(a[2]), "r"(a[3]), "r"(b0), "r"(b1));
}

// ---- smem layout (u32 indices), row stride 36 => banks 4*gr+cq (conflict-free)
#define STRW   36
#define S_XHI  0
#define S_XLO  (S_XHI + 128 * STRW)        // 4608
#define S_EHI  (S_XLO + 128 * STRW)        // 9216
#define S_ELO  (S_EHI + 128 * STRW)        // 13824
#define S_QS   (S_ELO + 128 * STRW)        // 18432
#define S_SB   (S_QS + KCOD)               // 18944
#define S_RED  (S_SB + 128)                // 19072
#define S_SIDX (S_RED + 8)                 // 19080
#define SMEM_U32 (S_SIDX + 128)            // 19208
#define SMEM_ASSIGN (SMEM_U32 * 4)         // 76832 B -> 2 CTAs/SM

// ============================================================
// Kernel 0: zero accumulators
// ============================================================
__global__ void k_zero() {
    int i = blockIdx.x * 512 + threadIdx.x;
    if (i < KCOD * CC) g_sums[i] = 0.0f;
    if (i < KCOD)      g_counts[i] = 0.0f;
    if (i == 0)        g_loss = 0.0f;
}

// Padding: ncu captures global launch #4; order z,d,d,a,f puts k_assign there.
__global__ void k_dummy() {}

// ============================================================
// Kernel 1: fp16 hi/lo 3-product mma.sync assign + fused epilogue
// 1024 CTAs x 256 threads (2 CTAs/SM); 128 tokens/CTA;
// 8 warps x 16-token m-tiles; codebook in 4 chunks of 128 codes.
// m16n8k16: 4 k-steps x 3 passes x 8 n-tiles x 2 groups = 768 mma/warp.
// ============================================================
__global__ __launch_bounds__(256, 2)
void k_assign(const float* __restrict__ x,
              const float* __restrict__ cb,
              float* __restrict__ out) {
    extern __shared__ float sm[];
    uint32_t* smu = (uint32_t*)sm;
    int* sidx = (int*)(sm + S_SIDX);

    const int tid  = threadIdx.x;
    const int wid  = tid >> 5;
    const int lane = tid & 31;
    const int gr   = lane >> 2;     // 0..7
    const int cq   = lane & 3;      // 0..3

    const int blk = blockIdx.x;
    const int b   = blk >> 5;                 // 32 CTAs per image
    const int p0  = (blk & 31) << 7;          // token base in H*W
    const float* xbase = x + ((size_t)b << 18);

    // ---- stage x: token = tid&127, 32 channels (16 half2) per thread ----
    {
        const int tok = tid & 127;
        const int ch0 = (tid >> 7) * 16;                 // u32 offset
        const float* xp = xbase + ((size_t)(ch0 * 2) << 12) + p0 + tok;
        #pragma unroll
        for (int j = 0; j < 16; ++j) {
            float v0 = xp[(size_t)(2 * j)     << 12];
            float v1 = xp[(size_t)(2 * j + 1) << 12];
            uint32_t hi, lo;
            split2(v0, v1, hi, lo);
            smu[S_XHI + tok * STRW + ch0 + j] = hi;
            smu[S_XLO + tok * STRW + ch0 + j] = lo;
        }
    }
    // ---- stage qs = 0.5*|e_k|^2 (2 codes/thread) ----
    #pragma unroll
    for (int r = 0; r < 2; ++r) {
        int k = tid + r * 256;
        const float4* row = (const float4*)(cb + (size_t)k * CC);
        float s = 0.0f;
        #pragma unroll
        for (int j = 0; j < 16; ++j) {
            float4 v = __ldg(row + j);
            s += v.x * v.x + v.y * v.y + v.z * v.z + v.w * v.w;
        }
        sm[S_QS + k] = 0.5f * s;
    }
    __syncthreads();

    // ---- preload A fragments (16 tokens per warp, 4 k-steps, hi+lo) ----
    const int m0 = wid << 4;
    const int ra = m0 + gr, rb = ra + 8;
    uint32_t ahi[4][4], alo[4][4];
    #pragma unroll
    for (int ks = 0; ks < 4; ++ks) {
        int idx = ks * 8 + cq;
        ahi[ks][0] = smu[S_XHI + ra * STRW + idx];
        ahi[ks][1] = smu[S_XHI + rb * STRW + idx];
        ahi[ks][2] = smu[S_XHI + ra * STRW + idx + 4];
        ahi[ks][3] = smu[S_XHI + rb * STRW + idx + 4];
        alo[ks][0] = smu[S_XLO + ra * STRW + idx];
        alo[ks][1] = smu[S_XLO + rb * STRW + idx];
        alo[ks][2] = smu[S_XLO + ra * STRW + idx + 4];
        alo[ks][3] = smu[S_XLO + rb * STRW + idx + 4];
    }

    float best0 = 3.4e38f, best1 = 3.4e38f;
    int   bi0 = 0, bi1 = 0;

    // ---- chunk loop: 4 x 128 codes ----
    for (int chk = 0; chk < 4; ++chk) {
        __syncthreads();   // previous chunk fully consumed
        {   // stage e chunk: row = tid/2 (code), 32 channels per thread
            const int row = tid >> 1;
            const int ch0 = (tid & 1) * 16;              // u32 offset
            const float4* src = (const float4*)(cb + (size_t)(chk * 128 + row) * CC + ch0 * 2);
            #pragma unroll
            for (int j = 0; j < 8; ++j) {
                float4 v = __ldg(src + j);
                uint32_t h0, l0, h1, l1;
                split2(v.x, v.y, h0, l0);
                split2(v.z, v.w, h1, l1);
                smu[S_EHI + row * STRW + ch0 + 2 * j]     = h0;
                smu[S_EHI + row * STRW + ch0 + 2 * j + 1] = h1;
                smu[S_ELO + row * STRW + ch0 + 2 * j]     = l0;
                smu[S_ELO + row * STRW + ch0 + 2 * j + 1] = l1;
            }
        }
        __syncthreads();

        // 2 groups x 8 n-tiles (64 codes each), pass-major (ILP 8)
        for (int g = 0; g < 2; ++g) {
            float acc[8][4];
            #pragma unroll
            for (int t = 0; t < 8; ++t)
                #pragma unroll
                for (int i = 0; i < 4; ++i) acc[t][i] = 0.0f;

            const int n0 = g * 64;
            #pragma unroll
            for (int ks = 0; ks < 4; ++ks) {
                const int idx = ks * 8 + cq;
                uint32_t bh0[8], bh1[8], bl0[8], bl1[8];
                #pragma unroll
                for (int t = 0; t < 8; ++t) {
                    int nb = n0 + t * 8 + gr;
                    bh0[t] = smu[S_EHI + nb * STRW + idx];
                    bh1[t] = smu[S_EHI + nb * STRW + idx + 4];
                    bl0[t] = smu[S_ELO + nb * STRW + idx];
                    bl1[t] = smu[S_ELO + nb * STRW + idx + 4];
                }
                #pragma unroll
                for (int t = 0; t < 8; ++t) mma16(acc[t], ahi[ks], bh0[t], bh1[t]);
                #pragma unroll
                for (int t = 0; t < 8; ++t) mma16(acc[t], alo[ks], bh0[t], bh1[t]);
                #pragma unroll
                for (int t = 0; t < 8; ++t) mma16(acc[t], ahi[ks], bl0[t], bl1[t]);
            }
            #pragma unroll
            for (int t = 0; t < 8; ++t) {
                int kb = chk * 128 + n0 + t * 8 + 2 * cq;
                float q0 = sm[S_QS + kb], q1 = sm[S_QS + kb + 1];
                float d00 = q0 - acc[t][0], d01 = q1 - acc[t][1];
                float d10 = q0 - acc[t][2], d11 = q1 - acc[t][3];
                if (d00 < best0) { best0 = d00; bi0 = kb; }
                if (d01 < best0) { best0 = d01; bi0 = kb + 1; }
                if (d10 < best1) { best1 = d10; bi1 = kb; }
                if (d11 < best1) { best1 = d11; bi1 = kb + 1; }
            }
        }
    }

    // ---- quad argmin reduce (lanes sharing a token: xor 1, xor 2) ----
    #pragma unroll
    for (int m = 1; m <= 2; m <<= 1) {
        float ob0 = __shfl_xor_sync(0xffffffffu, best0, m);
        int   oi0 = __shfl_xor_sync(0xffffffffu, bi0,   m);
        if (ob0 < best0 || (ob0 == best0 && oi0 < bi0)) { best0 = ob0; bi0 = oi0; }
        float ob1 = __shfl_xor_sync(0xffffffffu, best1, m);
        int   oi1 = __shfl_xor_sync(0xffffffffu, bi1,   m);
        if (ob1 < best1 || (ob1 == best1 && oi1 < bi1)) { best1 = ob1; bi1 = oi1; }
    }
    if (cq == 0) {
        sidx[ra] = bi0; sm[S_SB + ra] = best0;
        sidx[rb] = bi1; sm[S_SB + rb] = best1;
    }
    __syncthreads();

    // ---- loss + counts + segment sums (threads 0..127, x re-read L2-hot) ----
    if (tid < 128) {
        const float* xq = xbase + p0 + tid;
        float xr[64];
        #pragma unroll
        for (int c = 0; c < 64; ++c) xr[c] = xq[(size_t)c << 12];
        float xsq = 0.0f;
        #pragma unroll
        for (int c = 0; c < 64; ++c) xsq += xr[c] * xr[c];

        int bi = sidx[tid];
        atomicAdd(&g_counts[bi], 1.0f);
        float* srow = g_sums + bi * CC;
        #pragma unroll
        for (int i = 0; i < 16; ++i)
            red4(srow + i * 4, xr[4*i], xr[4*i+1], xr[4*i+2], xr[4*i+3]);

        float lsum = warp_red(xsq + 2.0f * sm[S_SB + tid]);
        if (lane == 0) sm[S_RED + wid] = lsum;
    }
    __syncthreads();
    if (tid == 0)
        atomicAdd(&g_loss, sm[S_RED+0] + sm[S_RED+1] + sm[S_RED+2] + sm[S_RED+3]);

    // ---- quantized output: 2 threads/token, coalesced STG ----
    {
        const int tok   = tid & 127;
        const int chalf = tid >> 7;
        const int bi    = sidx[tok];
        float* ob = out + ((size_t)b << 18) + p0 + tok;
        const float4* er = (const float4*)(cb + (size_t)bi * CC) + chalf * 8;
        #pragma unroll
        for (int j = 0; j < 8; ++j) {
            float4 v = __ldg(er + j);
            int c = chalf * 32 + 4 * j;
            ob[(size_t)(c + 0) << 12] = v.x;
            ob[(size_t)(c + 1) << 12] = v.y;
            ob[(size_t)(c + 2) << 12] = v.z;
            ob[(size_t)(c + 3) << 12] = v.w;
        }
    }
}

// ============================================================
// Kernel 2: EMA update + smoothing + new codebook + scalars
// ============================================================
__global__ __launch_bounds__(512)
void k_final(const float* __restrict__ ema_cs,
             const float* __restrict__ ema_w,
             float* __restrict__ out) {
    __shared__ float smc[KCOD];
    __shared__ float rn[16], ru[16];
    __shared__ float s_n, s_u;

    const int t = threadIdx.x;
    float cnt = g_counts[t];
    float ncs = 0.99f * ema_cs[t] + 0.01f * cnt;

    float nv = warp_red(ncs);
    float uv = warp_red(cnt > 0.0f ? 1.0f : 0.0f);
    if ((t & 31) == 0) { rn[t >> 5] = nv; ru[t >> 5] = uv; }
    __syncthreads();
    if (t == 0) {
        float a = 0.0f, u = 0.0f;
        #pragma unroll
        for (int i = 0; i < 16; ++i) { a += rn[i]; u += ru[i]; }
        s_n = a; s_u = u;
    }
    __syncthreads();

    smc[t] = (ncs + EPSF) / (s_n + (float)KCOD * EPSF) * s_n;
    __syncthreads();

    int i = blockIdx.x * 512 + t;
    float nw = 0.99f * ema_w[i] + 0.01f * g_sums[i];
    out[CB_OFF + i] = nw / smc[i >> 6];

    if (blockIdx.x == 0 && t == 0) {
        out[LOSS_OFF] = g_loss * (1.0f / (float)OUT_ELEMS);
        out[UNIQ_OFF] = s_u;
    }
}

// ============================================================
extern "C" void kernel_launch(void* const* d_in, const int* in_sizes, int n_in,
                              void* d_out, int out_size) {
    const float* x   = (const float*)d_in[0];
    const float* cb  = (const float*)d_in[1];
    const float* ecs = (const float*)d_in[2];
    const float* ew  = (const float*)d_in[3];
    float* out = (float*)d_out;

    cudaFuncSetAttribute(k_assign, cudaFuncAttributeMaxDynamicSharedMemorySize, SMEM_ASSIGN);

    k_zero<<<65, 512>>>();
    k_dummy<<<1, 32>>>();   // pad so global launch #4 (ncu capture point)
    k_dummy<<<1, 32>>>();   // is k_assign
    k_assign<<<NTOK / 128, 256, SMEM_ASSIGN>>>(x, cb, out);
    k_final<<<64, 512>>>(ecs, ew, out);
}

// round 13
// speedup vs baseline: 2.0281x; 1.0049x over previous
#include <cuda_runtime.h>
#include <cuda_fp16.h>
#include <cstdint>

// Problem constants
#define CC    64
#define HWSZ  4096
#define NTOK  131072
#define KCOD  512
#define EPSF  1e-5f

// Output layout
#define OUT_ELEMS  8388608
#define LOSS_OFF   8388608
#define UNIQ_OFF   8388609
#define CB_OFF     8388610

// -------- device scratch --------
__device__ float g_counts[KCOD];
__device__ float g_sums[KCOD * CC];
__device__ float g_loss;

// -------- helpers --------
__device__ __forceinline__ void red4(float* p, float a, float b, float c, float d) {
    asm volatile("red.global.add.v4.f32 [%0], {%1, %2, %3, %4};"
                 :: "l"(p), "f"(a), "f"(b), "f"(c), "f"(d) : "memory");
}
__device__ __forceinline__ float warp_red(float v) {
    #pragma unroll
    for (int o = 16; o; o >>= 1) v += __shfl_xor_sync(0xffffffffu, v, o);
    return v;
}
// pack hi halves of (a,b) and lo halves (residuals) as half2-in-u32
__device__ __forceinline__ void split2(float a, float b, uint32_t& hi, uint32_t& lo) {
    __half ha = __float2half_rn(a), hb = __float2half_rn(b);
    __half la = __float2half_rn(a - __half2float(ha));
    __half lb = __float2half_rn(b - __half2float(hb));
    __half2 h = __halves2half2(ha, hb), l = __halves2half2(la, lb);
    hi = *(uint32_t*)&h;  lo = *(uint32_t*)&l;
}
__device__ __forceinline__ void mma16(float* d, const uint32_t* a, uint32_t b0, uint32_t b1) {
    asm volatile(
        "mma.sync.aligned.m16n8k16.row.col.f32.f16.f16.f32 "
        "{%0,%1,%2,%3}, {%4,%5,%6,%7}, {%8,%9}, {%0,%1,%2,%3};"
        : "+f"(d[0]), "+f"(d[1]), "+f"(d[2]), "+f"(d[3])
        : "r"(a[0]), "r"(a[1]), "r"(a[2]), "r"(a[3]), "r"(b0), "r"(b1));
}

// ---- packed fragment smem layout ----
// Row (token or code) = 80 u32 (64 data + 16 pad; quad-stride 20 ≡ 4 mod 8).
// Slot (ks,cq) at u32 offset (ks*4+cq)*4 holds the 16B quad
// [hi(idx), hi(idx+4), lo(idx), lo(idx+4)], idx = ks*8+cq (u32 = half2).
// LDS.128 phase group (gr∈{0,1}, cq∈0..3): quad-bank = (4gr+cq+const) mod 8
// -> all 8 distinct -> conflict-free mainloop reads.
#define STRW   80
#define S_X    0
#define S_E    (S_X + 128 * STRW)          // 10240
#define S_QS   (S_E + 128 * STRW)          // 20480
#define S_SB   (S_QS + KCOD)               // 20992
#define S_RED  (S_SB + 128)                // 21120
#define S_SIDX (S_RED + 8)                 // 21128
#define SMEM_U32 (S_SIDX + 128)            // 21256
#define SMEM_ASSIGN (SMEM_U32 * 4)         // 85024 B -> 2 CTAs/SM

// ============================================================
// Kernel 0: zero accumulators
// ============================================================
__global__ void k_zero() {
    int i = blockIdx.x * 512 + threadIdx.x;
    if (i < KCOD * CC) g_sums[i] = 0.0f;
    if (i < KCOD)      g_counts[i] = 0.0f;
    if (i == 0)        g_loss = 0.0f;
}

// Padding: ncu captures global launch #4; order z,d,d,a,f puts k_assign there.
__global__ void k_dummy() {}

// ============================================================
// Kernel 1: fp16 hi/lo 3-product mma.sync assign + fused epilogue
// 1024 CTAs x 256 threads (2 CTAs/SM); 128 tokens/CTA;
// 8 warps x 16-token m-tiles; codebook in 4 chunks of 128 codes.
// Mainloop fragment loads are conflict-free LDS.128 (packed hi/lo quads).
// ============================================================
__global__ __launch_bounds__(256, 2)
void k_assign(const float* __restrict__ x,
              const float* __restrict__ cb,
              float* __restrict__ out) {
    extern __shared__ float sm[];
    uint32_t* smu = (uint32_t*)sm;
    int* sidx = (int*)(sm + S_SIDX);

    const int tid  = threadIdx.x;
    const int wid  = tid >> 5;
    const int lane = tid & 31;
    const int gr   = lane >> 2;     // 0..7
    const int cq   = lane & 3;      // 0..3

    const int blk = blockIdx.x;
    const int b   = blk >> 5;                 // 32 CTAs per image
    const int p0  = (blk & 31) << 7;          // token base in H*W
    const float* xbase = x + ((size_t)b << 18);

    // ---- stage x (packed): token = tid&127, 2 cq-columns per thread ----
    {
        const int tok = tid & 127;
        const int h   = tid >> 7;             // 0/1 -> cq in {2h, 2h+1}
        const float* xp = xbase + p0 + tok;
        #pragma unroll
        for (int ks = 0; ks < 4; ++ks) {
            #pragma unroll
            for (int c = 0; c < 2; ++c) {
                int cqs = 2 * h + c;
                int c0  = 16 * ks + 2 * cqs;  // channel of u32 idx = ks*8+cqs
                float v0 = xp[(size_t)(c0    ) << 12];
                float v1 = xp[(size_t)(c0 + 1) << 12];
                float v2 = xp[(size_t)(c0 + 8) << 12];
                float v3 = xp[(size_t)(c0 + 9) << 12];
                uint32_t h0, l0, h1, l1;
                split2(v0, v1, h0, l0);
                split2(v2, v3, h1, l1);
                *(uint4*)(smu + S_X + tok * STRW + (ks * 4 + cqs) * 4) =
                    make_uint4(h0, h1, l0, l1);
            }
        }
    }
    // ---- stage qs = 0.5*|e_k|^2 (2 codes/thread) ----
    #pragma unroll
    for (int r = 0; r < 2; ++r) {
        int k = tid + r * 256;
        const float4* row = (const float4*)(cb + (size_t)k * CC);
        float s = 0.0f;
        #pragma unroll
        for (int j = 0; j < 16; ++j) {
            float4 v = __ldg(row + j);
            s += v.x * v.x + v.y * v.y + v.z * v.z + v.w * v.w;
        }
        sm[S_QS + k] = 0.5f * s;
    }
    __syncthreads();

    // ---- preload A fragments: 2 LDS.128 per k-step ----
    const int m0 = wid << 4;
    const int ra = m0 + gr, rb = ra + 8;
    uint32_t ahi[4][4], alo[4][4];
    #pragma unroll
    for (int ks = 0; ks < 4; ++ks) {
        uint4 va = *(const uint4*)(smu + S_X + ra * STRW + (ks * 4 + cq) * 4);
        uint4 vb = *(const uint4*)(smu + S_X + rb * STRW + (ks * 4 + cq) * 4);
        ahi[ks][0] = va.x; ahi[ks][1] = vb.x; ahi[ks][2] = va.y; ahi[ks][3] = vb.y;
        alo[ks][0] = va.z; alo[ks][1] = vb.z; alo[ks][2] = va.w; alo[ks][3] = vb.w;
    }

    float best0 = 3.4e38f, best1 = 3.4e38f;
    int   bi0 = 0, bi1 = 0;

    // ---- chunk loop: 4 x 128 codes ----
    for (int chk = 0; chk < 4; ++chk) {
        __syncthreads();   // previous chunk fully consumed
        {   // stage e chunk (packed): row = tid/2, 2 cq-columns per thread
            const int row = tid >> 1;
            const int h   = tid & 1;
            const float* src = cb + (size_t)(chk * 128 + row) * CC;
            #pragma unroll
            for (int ks = 0; ks < 4; ++ks) {
                #pragma unroll
                for (int c = 0; c < 2; ++c) {
                    int cqs = 2 * h + c;
                    int c0  = 16 * ks + 2 * cqs;
                    float2 p0v = __ldg((const float2*)(src + c0));
                    float2 p1v = __ldg((const float2*)(src + c0 + 8));
                    uint32_t h0, l0, h1, l1;
                    split2(p0v.x, p0v.y, h0, l0);
                    split2(p1v.x, p1v.y, h1, l1);
                    *(uint4*)(smu + S_E + row * STRW + (ks * 4 + cqs) * 4) =
                        make_uint4(h0, h1, l0, l1);
                }
            }
        }
        __syncthreads();

        // 2 groups x 8 n-tiles (64 codes each), pass-major (ILP 8)
        for (int g = 0; g < 2; ++g) {
            float acc[8][4];
            #pragma unroll
            for (int t = 0; t < 8; ++t)
                #pragma unroll
                for (int i = 0; i < 4; ++i) acc[t][i] = 0.0f;

            const int n0 = g * 64;
            #pragma unroll
            for (int ks = 0; ks < 4; ++ks) {
                uint4 bf[8];
                #pragma unroll
                for (int t = 0; t < 8; ++t) {
                    int nb = n0 + t * 8 + gr;
                    bf[t] = *(const uint4*)(smu + S_E + nb * STRW + (ks * 4 + cq) * 4);
                }
                #pragma unroll
                for (int t = 0; t < 8; ++t) mma16(acc[t], ahi[ks], bf[t].x, bf[t].y);
                #pragma unroll
                for (int t = 0; t < 8; ++t) mma16(acc[t], alo[ks], bf[t].x, bf[t].y);
                #pragma unroll
                for (int t = 0; t < 8; ++t) mma16(acc[t], ahi[ks], bf[t].z, bf[t].w);
            }
            #pragma unroll
            for (int t = 0; t < 8; ++t) {
                int kb = chk * 128 + n0 + t * 8 + 2 * cq;
                float q0 = sm[S_QS + kb], q1 = sm[S_QS + kb + 1];
                float d00 = q0 - acc[t][0], d01 = q1 - acc[t][1];
                float d10 = q0 - acc[t][2], d11 = q1 - acc[t][3];
                if (d00 < best0) { best0 = d00; bi0 = kb; }
                if (d01 < best0) { best0 = d01; bi0 = kb + 1; }
                if (d10 < best1) { best1 = d10; bi1 = kb; }
                if (d11 < best1) { best1 = d11; bi1 = kb + 1; }
            }
        }
    }

    // ---- quad argmin reduce (lanes sharing a token: xor 1, xor 2) ----
    #pragma unroll
    for (int m = 1; m <= 2; m <<= 1) {
        float ob0 = __shfl_xor_sync(0xffffffffu, best0, m);
        int   oi0 = __shfl_xor_sync(0xffffffffu, bi0,   m);
        if (ob0 < best0 || (ob0 == best0 && oi0 < bi0)) { best0 = ob0; bi0 = oi0; }
        float ob1 = __shfl_xor_sync(0xffffffffu, best1, m);
        int   oi1 = __shfl_xor_sync(0xffffffffu, bi1,   m);
        if (ob1 < best1 || (ob1 == best1 && oi1 < bi1)) { best1 = ob1; bi1 = oi1; }
    }
    if (cq == 0) {
        sidx[ra] = bi0; sm[S_SB + ra] = best0;
        sidx[rb] = bi1; sm[S_SB + rb] = best1;
    }
    __syncthreads();

    // ---- loss + counts + segment sums (threads 0..127, x re-read L2-hot) ----
    if (tid < 128) {
        const float* xq = xbase + p0 + tid;
        float xr[64];
        #pragma unroll
        for (int c = 0; c < 64; ++c) xr[c] = xq[(size_t)c << 12];
        float xsq = 0.0f;
        #pragma unroll
        for (int c = 0; c < 64; ++c) xsq += xr[c] * xr[c];

        int bi = sidx[tid];
        atomicAdd(&g_counts[bi], 1.0f);
        float* srow = g_sums + bi * CC;
        #pragma unroll
        for (int i = 0; i < 16; ++i)
            red4(srow + i * 4, xr[4*i], xr[4*i+1], xr[4*i+2], xr[4*i+3]);

        float lsum = warp_red(xsq + 2.0f * sm[S_SB + tid]);
        if (lane == 0) sm[S_RED + wid] = lsum;
    }
    __syncthreads();
    if (tid == 0)
        atomicAdd(&g_loss, sm[S_RED+0] + sm[S_RED+1] + sm[S_RED+2] + sm[S_RED+3]);

    // ---- quantized output: 2 threads/token, coalesced STG ----
    {
        const int tok   = tid & 127;
        const int chalf = tid >> 7;
        const int bi    = sidx[tok];
        float* ob = out + ((size_t)b << 18) + p0 + tok;
        const float4* er = (const float4*)(cb + (size_t)bi * CC) + chalf * 8;
        #pragma unroll
        for (int j = 0; j < 8; ++j) {
            float4 v = __ldg(er + j);
            int c = chalf * 32 + 4 * j;
            ob[(size_t)(c + 0) << 12] = v.x;
            ob[(size_t)(c + 1) << 12] = v.y;
            ob[(size_t)(c + 2) << 12] = v.z;
            ob[(size_t)(c + 3) << 12] = v.w;
        }
    }
}

// ============================================================
// Kernel 2: EMA update + smoothing + new codebook + scalars
// ============================================================
__global__ __launch_bounds__(512)
void k_final(const float* __restrict__ ema_cs,
             const float* __restrict__ ema_w,
             float* __restrict__ out) {
    __shared__ float smc[KCOD];
    __shared__ float rn[16], ru[16];
    __shared__ float s_n, s_u;

    const int t = threadIdx.x;
    float cnt = g_counts[t];
    float ncs = 0.99f * ema_cs[t] + 0.01f * cnt;

    float nv = warp_red(ncs);
    float uv = warp_red(cnt > 0.0f ? 1.0f : 0.0f);
    if ((t & 31) == 0) { rn[t >> 5] = nv; ru[t >> 5] = uv; }
    __syncthreads();
    if (t == 0) {
        float a = 0.0f, u = 0.0f;
        #pragma unroll
        for (int i = 0; i < 16; ++i) { a += rn[i]; u += ru[i]; }
        s_n = a; s_u = u;
    }
    __syncthreads();

    smc[t] = (ncs + EPSF) / (s_n + (float)KCOD * EPSF) * s_n;
    __syncthreads();

    int i = blockIdx.x * 512 + t;
    float nw = 0.99f * ema_w[i] + 0.01f * g_sums[i];
    out[CB_OFF + i] = nw / smc[i >> 6];

    if (blockIdx.x == 0 && t == 0) {
        out[LOSS_OFF] = g_loss * (1.0f / (float)OUT_ELEMS);
        out[UNIQ_OFF] = s_u;
    }
}

// ============================================================
extern "C" void kernel_launch(void* const* d_in, const int* in_sizes, int n_in,
                              void* d_out, int out_size) {
    const float* x   = (const float*)d_in[0];
    const float* cb  = (const float*)d_in[1];
    const float* ecs = (const float*)d_in[2];
    const float* ew  = (const float*)d_in[3];
    float* out = (float*)d_out;

    cudaFuncSetAttribute(k_assign, cudaFuncAttributeMaxDynamicSharedMemorySize, SMEM_ASSIGN);

    k_zero<<<65, 512>>>();
    k_dummy<<<1, 32>>>();   // pad so global launch #4 (ncu capture point)
    k_dummy<<<1, 32>>>();   // is k_assign
    k_assign<<<NTOK / 128, 256, SMEM_ASSIGN>>>(x, cb, out);
    k_final<<<64, 512>>>(ecs, ew, out);
}

// round 14
// speedup vs baseline: 2.6429x; 1.3031x over previous
#include <cuda_runtime.h>
#include <cuda_fp16.h>
#include <cstdint>

// Problem constants
#define CC    64
#define HWSZ  4096
#define NTOK  131072
#define KCOD  512
#define EPSF  1e-5f

// Output layout
#define OUT_ELEMS  8388608
#define LOSS_OFF   8388608
#define UNIQ_OFF   8388609
#define CB_OFF     8388610

// -------- device scratch --------
__device__ float g_counts[KCOD];
__device__ float g_sums[KCOD * CC];
__device__ float g_q[KCOD];
__device__ float g_loss;

// -------- helpers --------
__device__ __forceinline__ void red4(float* p, float a, float b, float c, float d) {
    asm volatile("red.global.add.v4.f32 [%0], {%1, %2, %3, %4};"
                 :: "l"(p), "f"(a), "f"(b), "f"(c), "f"(d) : "memory");
}
__device__ __forceinline__ float warp_red(float v) {
    #pragma unroll
    for (int o = 16; o; o >>= 1) v += __shfl_xor_sync(0xffffffffu, v, o);
    return v;
}
// pack hi halves of (a,b) and lo halves (residuals) as half2-in-u32
__device__ __forceinline__ void split2(float a, float b, uint32_t& hi, uint32_t& lo) {
    __half ha = __float2half_rn(a), hb = __float2half_rn(b);
    __half la = __float2half_rn(a - __half2float(ha));
    __half lb = __float2half_rn(b - __half2float(hb));
    __half2 h = __halves2half2(ha, hb), l = __halves2half2(la, lb);
    hi = *(uint32_t*)&h;  lo = *(uint32_t*)&l;
}
__device__ __forceinline__ void mma16(float* d, const uint32_t* a, uint32_t b0, uint32_t b1) {
    asm volatile(
        "mma.sync.aligned.m16n8k16.row.col.f32.f16.f16.f32 "
        "{%0,%1,%2,%3}, {%4,%5,%6,%7}, {%8,%9}, {%0,%1,%2,%3};"
        : "+f"(d[0]), "+f"(d[1]), "+f"(d[2]), "+f"(d[3])
        : "r"(a[0]), "r"(a[1]), "r"(a[2]), "r"(a[3]), "r"(b0), "r"(b1));
}

// ---- packed fragment smem layout ----
// Row (token or code) = 80 u32 (64 data + 16 pad; quad-stride 20 ≡ 4 mod 8).
// Slot (ks,cq) at u32 offset (ks*4+cq)*4 holds the 16B quad
// [hi(idx), hi(idx+4), lo(idx), lo(idx+4)], idx = ks*8+cq (u32 = half2).
#define STRW   80
#define S_X    0
#define S_E    (S_X + 128 * STRW)          // 10240
#define S_QS   (S_E + 128 * STRW)          // 20480
#define S_SB   (S_QS + KCOD)               // 20992
#define S_RED  (S_SB + 128)                // 21120
#define S_SIDX (S_RED + 8)                 // 21128
#define SMEM_U32 (S_SIDX + 128)            // 21256
#define SMEM_ASSIGN (SMEM_U32 * 4)         // 85024 B -> 2 CTAs/SM

// ============================================================
// Kernel 0: zero accumulators + precompute q[k] = 0.5*|e_k|^2
// (q computed ONCE here instead of redundantly in 1024 CTAs)
// ============================================================
__global__ void k_zero(const float* __restrict__ cb) {
    int i = blockIdx.x * 512 + threadIdx.x;
    if (i < KCOD * CC) g_sums[i] = 0.0f;
    if (i < KCOD) {
        g_counts[i] = 0.0f;
        const float4* row = (const float4*)(cb + (size_t)i * CC);
        float s = 0.0f;
        #pragma unroll
        for (int j = 0; j < 16; ++j) {
            float4 v = __ldg(row + j);
            s += v.x * v.x + v.y * v.y + v.z * v.z + v.w * v.w;
        }
        g_q[i] = 0.5f * s;
    }
    if (i == 0) g_loss = 0.0f;
}

// Padding: ncu captures global launch #4; order z,d,d,a,f puts k_assign there.
__global__ void k_dummy() {}

// ============================================================
// Kernel 1: fp16 hi/lo 3-product mma.sync assign + fused epilogue
// 1024 CTAs x 256 threads (2 CTAs/SM); 128 tokens/CTA;
// 8 warps x 16-token m-tiles; codebook in 4 chunks of 128 codes.
// ============================================================
__global__ __launch_bounds__(256, 2)
void k_assign(const float* __restrict__ x,
              const float* __restrict__ cb,
              float* __restrict__ out) {
    extern __shared__ float sm[];
    uint32_t* smu = (uint32_t*)sm;
    int* sidx = (int*)(sm + S_SIDX);

    const int tid  = threadIdx.x;
    const int wid  = tid >> 5;
    const int lane = tid & 31;
    const int gr   = lane >> 2;     // 0..7
    const int cq   = lane & 3;      // 0..3

    const int blk = blockIdx.x;
    const int b   = blk >> 5;                 // 32 CTAs per image
    const int p0  = (blk & 31) << 7;          // token base in H*W
    const float* xbase = x + ((size_t)b << 18);

    // ---- stage x (packed): token = tid&127, 2 cq-columns per thread ----
    {
        const int tok = tid & 127;
        const int h   = tid >> 7;             // 0/1 -> cq in {2h, 2h+1}
        const float* xp = xbase + p0 + tok;
        #pragma unroll
        for (int ks = 0; ks < 4; ++ks) {
            #pragma unroll
            for (int c = 0; c < 2; ++c) {
                int cqs = 2 * h + c;
                int c0  = 16 * ks + 2 * cqs;  // channel of u32 idx = ks*8+cqs
                float v0 = xp[(size_t)(c0    ) << 12];
                float v1 = xp[(size_t)(c0 + 1) << 12];
                float v2 = xp[(size_t)(c0 + 8) << 12];
                float v3 = xp[(size_t)(c0 + 9) << 12];
                uint32_t h0, l0, h1, l1;
                split2(v0, v1, h0, l0);
                split2(v2, v3, h1, l1);
                *(uint4*)(smu + S_X + tok * STRW + (ks * 4 + cqs) * 4) =
                    make_uint4(h0, h1, l0, l1);
            }
        }
    }
    // ---- stage qs: coalesced copy of precomputed g_q ----
    sm[S_QS + tid]       = g_q[tid];
    sm[S_QS + tid + 256] = g_q[tid + 256];
    __syncthreads();

    // ---- preload A fragments: 2 LDS.128 per k-step ----
    const int m0 = wid << 4;
    const int ra = m0 + gr, rb = ra + 8;
    uint32_t ahi[4][4], alo[4][4];
    #pragma unroll
    for (int ks = 0; ks < 4; ++ks) {
        uint4 va = *(const uint4*)(smu + S_X + ra * STRW + (ks * 4 + cq) * 4);
        uint4 vb = *(const uint4*)(smu + S_X + rb * STRW + (ks * 4 + cq) * 4);
        ahi[ks][0] = va.x; ahi[ks][1] = vb.x; ahi[ks][2] = va.y; ahi[ks][3] = vb.y;
        alo[ks][0] = va.z; alo[ks][1] = vb.z; alo[ks][2] = va.w; alo[ks][3] = vb.w;
    }

    float best0 = 3.4e38f, best1 = 3.4e38f;
    int   bi0 = 0, bi1 = 0;

    // ---- chunk loop: 4 x 128 codes ----
    for (int chk = 0; chk < 4; ++chk) {
        __syncthreads();   // previous chunk fully consumed
        {   // stage e chunk (packed): row = tid/2; float4-pair loads per ks
            const int row = tid >> 1;
            const int h   = tid & 1;
            const float* src = cb + (size_t)(chk * 128 + row) * CC;
            #pragma unroll
            for (int ks = 0; ks < 4; ++ks) {
                int c0 = 16 * ks + 4 * h;          // chans c0..c0+3, c0+8..c0+11
                float4 fa = __ldg((const float4*)(src + c0));
                float4 fb = __ldg((const float4*)(src + c0 + 8));
                uint32_t ha0, la0, hb0, lb0, ha1, la1, hb1, lb1;
                split2(fa.x, fa.y, ha0, la0);      // quad (ks, 2h) low pair
                split2(fb.x, fb.y, hb0, lb0);      // quad (ks, 2h) high pair
                split2(fa.z, fa.w, ha1, la1);      // quad (ks, 2h+1) low pair
                split2(fb.z, fb.w, hb1, lb1);      // quad (ks, 2h+1) high pair
                *(uint4*)(smu + S_E + row * STRW + (ks * 4 + 2 * h) * 4) =
                    make_uint4(ha0, hb0, la0, lb0);
                *(uint4*)(smu + S_E + row * STRW + (ks * 4 + 2 * h + 1) * 4) =
                    make_uint4(ha1, hb1, la1, lb1);
            }
        }
        __syncthreads();

        // 2 groups x 8 n-tiles (64 codes each), pass-major (ILP 8)
        for (int g = 0; g < 2; ++g) {
            float acc[8][4];
            #pragma unroll
            for (int t = 0; t < 8; ++t)
                #pragma unroll
                for (int i = 0; i < 4; ++i) acc[t][i] = 0.0f;

            const int n0 = g * 64;
            #pragma unroll
            for (int ks = 0; ks < 4; ++ks) {
                uint4 bf[8];
                #pragma unroll
                for (int t = 0; t < 8; ++t) {
                    int nb = n0 + t * 8 + gr;
                    bf[t] = *(const uint4*)(smu + S_E + nb * STRW + (ks * 4 + cq) * 4);
                }
                #pragma unroll
                for (int t = 0; t < 8; ++t) mma16(acc[t], ahi[ks], bf[t].x, bf[t].y);
                #pragma unroll
                for (int t = 0; t < 8; ++t) mma16(acc[t], alo[ks], bf[t].x, bf[t].y);
                #pragma unroll
                for (int t = 0; t < 8; ++t) mma16(acc[t], ahi[ks], bf[t].z, bf[t].w);
            }
            #pragma unroll
            for (int t = 0; t < 8; ++t) {
                int kb = chk * 128 + n0 + t * 8 + 2 * cq;
                float q0 = sm[S_QS + kb], q1 = sm[S_QS + kb + 1];
                float d00 = q0 - acc[t][0], d01 = q1 - acc[t][1];
                float d10 = q0 - acc[t][2], d11 = q1 - acc[t][3];
                if (d00 < best0) { best0 = d00; bi0 = kb; }
                if (d01 < best0) { best0 = d01; bi0 = kb + 1; }
                if (d10 < best1) { best1 = d10; bi1 = kb; }
                if (d11 < best1) { best1 = d11; bi1 = kb + 1; }
            }
        }
    }

    // ---- quad argmin reduce (lanes sharing a token: xor 1, xor 2) ----
    #pragma unroll
    for (int m = 1; m <= 2; m <<= 1) {
        float ob0 = __shfl_xor_sync(0xffffffffu, best0, m);
        int   oi0 = __shfl_xor_sync(0xffffffffu, bi0,   m);
        if (ob0 < best0 || (ob0 == best0 && oi0 < bi0)) { best0 = ob0; bi0 = oi0; }
        float ob1 = __shfl_xor_sync(0xffffffffu, best1, m);
        int   oi1 = __shfl_xor_sync(0xffffffffu, bi1,   m);
        if (ob1 < best1 || (ob1 == best1 && oi1 < bi1)) { best1 = ob1; bi1 = oi1; }
    }
    if (cq == 0) {
        sidx[ra] = bi0; sm[S_SB + ra] = best0;
        sidx[rb] = bi1; sm[S_SB + rb] = best1;
    }
    __syncthreads();

    // ---- loss + counts + segment sums (threads 0..127, x re-read L2-hot) ----
    if (tid < 128) {
        const float* xq = xbase + p0 + tid;
        float xr[64];
        #pragma unroll
        for (int c = 0; c < 64; ++c) xr[c] = xq[(size_t)c << 12];
        float xsq = 0.0f;
        #pragma unroll
        for (int c = 0; c < 64; ++c) xsq += xr[c] * xr[c];

        int bi = sidx[tid];
        atomicAdd(&g_counts[bi], 1.0f);
        float* srow = g_sums + bi * CC;
        #pragma unroll
        for (int i = 0; i < 16; ++i)
            red4(srow + i * 4, xr[4*i], xr[4*i+1], xr[4*i+2], xr[4*i+3]);

        float lsum = warp_red(xsq + 2.0f * sm[S_SB + tid]);
        if (lane == 0) sm[S_RED + wid] = lsum;
    }
    __syncthreads();
    if (tid == 0)
        atomicAdd(&g_loss, sm[S_RED+0] + sm[S_RED+1] + sm[S_RED+2] + sm[S_RED+3]);

    // ---- quantized output: 2 threads/token, coalesced STG ----
    {
        const int tok   = tid & 127;
        const int chalf = tid >> 7;
        const int bi    = sidx[tok];
        float* ob = out + ((size_t)b << 18) + p0 + tok;
        const float4* er = (const float4*)(cb + (size_t)bi * CC) + chalf * 8;
        #pragma unroll
        for (int j = 0; j < 8; ++j) {
            float4 v = __ldg(er + j);
            int c = chalf * 32 + 4 * j;
            ob[(size_t)(c + 0) << 12] = v.x;
            ob[(size_t)(c + 1) << 12] = v.y;
            ob[(size_t)(c + 2) << 12] = v.z;
            ob[(size_t)(c + 3) << 12] = v.w;
        }
    }
}

// ============================================================
// Kernel 2: EMA update + smoothing + new codebook + scalars
// ============================================================
__global__ __launch_bounds__(512)
void k_final(const float* __restrict__ ema_cs,
             const float* __restrict__ ema_w,
             float* __restrict__ out) {
    __shared__ float smc[KCOD];
    __shared__ float rn[16], ru[16];
    __shared__ float s_n, s_u;

    const int t = threadIdx.x;
    float cnt = g_counts[t];
    float ncs = 0.99f * ema_cs[t] + 0.01f * cnt;

    float nv = warp_red(ncs);
    float uv = warp_red(cnt > 0.0f ? 1.0f : 0.0f);
    if ((t & 31) == 0) { rn[t >> 5] = nv; ru[t >> 5] = uv; }
    __syncthreads();
    if (t == 0) {
        float a = 0.0f, u = 0.0f;
        #pragma unroll
        for (int i = 0; i < 16; ++i) { a += rn[i]; u += ru[i]; }
        s_n = a; s_u = u;
    }
    __syncthreads();

    smc[t] = (ncs + EPSF) / (s_n + (float)KCOD * EPSF) * s_n;
    __syncthreads();

    int i = blockIdx.x * 512 + t;
    float nw = 0.99f * ema_w[i] + 0.01f * g_sums[i];
    out[CB_OFF + i] = nw / smc[i >> 6];

    if (blockIdx.x == 0 && t == 0) {
        out[LOSS_OFF] = g_loss * (1.0f / (float)OUT_ELEMS);
        out[UNIQ_OFF] = s_u;
    }
}

// ============================================================
extern "C" void kernel_launch(void* const* d_in, const int* in_sizes, int n_in,
                              void* d_out, int out_size) {
    const float* x   = (const float*)d_in[0];
    const float* cb  = (const float*)d_in[1];
    const float* ecs = (const float*)d_in[2];
    const float* ew  = (const float*)d_in[3];
    float* out = (float*)d_out;

    cudaFuncSetAttribute(k_assign, cudaFuncAttributeMaxDynamicSharedMemorySize, SMEM_ASSIGN);

    k_zero<<<65, 512>>>(cb);
    k_dummy<<<1, 32>>>();   // pad so global launch #4 (ncu capture point)
    k_dummy<<<1, 32>>>();   // is k_assign
    k_assign<<<NTOK / 128, 256, SMEM_ASSIGN>>>(x, cb, out);
    k_final<<<64, 512>>>(ecs, ew, out);
}